// round 15
// baseline (speedup 1.0000x reference)
#include <cuda_runtime.h>
#include <cuda_fp16.h>
#include <cstdint>
#include <cstddef>

// ---------------------------------------------------------------------------
// Cayley-Dickson sign table:  e_i * e_j = sign(i,j) * e_{i XOR j}
// ---------------------------------------------------------------------------
constexpr int cdsign(int i, int j, int n) {
    return (n == 1) ? 1
         : (i < n/2 && j < n/2) ? cdsign(i, j, n/2)
         : (i < n/2)            ? cdsign(j - n/2, i, n/2)
         : (j < n/2)            ? cdsign(i - n/2, j, n/2) * (j == 0 ? 1 : -1)
         : -cdsign(j - n/2, i - n/2, n/2) * ((j - n/2) == 0 ? 1 : -1);
}
struct SgnTab { signed char v[16][16]; };
constexpr SgnTab make_sgn() {
    SgnTab t{};
    for (int i = 0; i < 16; ++i)
        for (int j = 0; j < 16; ++j)
            t.v[i][j] = (signed char)cdsign(i, j, 16);
    return t;
}
__constant__ SgnTab c_SGN = make_sgn();

// ---------------------------------------------------------------------------
static constexpr int C = 128, NPIX = 8 * 128 * 128;   // 131072

// residual buffers fp16 (calibrated error budget)
__device__ __align__(256) __half g_xt[NPIX * C];
__device__ __align__(256) __half g_y [NPIX * C];

// fp16 operand buffers
__device__ __align__(256) __half g_xn[NPIX * C];
__device__ __align__(256) __half g_yn[NPIX * C];
// weight (B^T, n-major rows of K) buffers
__device__ __align__(256) __half g_bt[2048 * 2048];
__device__ __align__(256) __half g_bp[128 * 128];
__device__ __align__(256) __half g_b1[512 * 128];
__device__ __align__(256) __half g_b2[128 * 512];

// ---------------------------------------------------------------------------
// PTX helpers
// ---------------------------------------------------------------------------
__device__ __forceinline__ uint32_t smem_u32(const void* p) {
    uint32_t a;
    asm("{ .reg .u64 t; cvta.to.shared.u64 t, %1; cvt.u32.u64 %0, t; }"
        : "=r"(a) : "l"(p));
    return a;
}
__device__ __forceinline__ void cp16(uint32_t dst, const void* src) {
    asm volatile("cp.async.cg.shared.global [%0], [%1], 16;" :: "r"(dst), "l"(src));
}
#define CP_COMMIT() asm volatile("cp.async.commit_group;" ::: "memory")
template<int N>
__device__ __forceinline__ void cp_wait() {
    asm volatile("cp.async.wait_group %0;" :: "n"(N) : "memory");
}
__device__ __forceinline__ void ldsm_x4(uint32_t addr, uint32_t* r) {
    asm volatile("ldmatrix.sync.aligned.m8n8.x4.shared.b16 {%0,%1,%2,%3}, [%4];"
        : "=r"(r[0]), "=r"(r[1]), "=r"(r[2]), "=r"(r[3]) : "r"(addr));
}
__device__ __forceinline__ void mma16816(float* c, const uint32_t* a, const uint32_t* b) {
    asm volatile("mma.sync.aligned.m16n8k16.row.col.f32.f16.f16.f32 "
        "{%0,%1,%2,%3}, {%4,%5,%6,%7}, {%8,%9}, {%0,%1,%2,%3};"
        : "+f"(c[0]), "+f"(c[1]), "+f"(c[2]), "+f"(c[3])
        : "r"(a[0]), "r"(a[1]), "r"(a[2]), "r"(a[3]), "r"(b[0]), "r"(b[1]));
}
__device__ __forceinline__ uint32_t swz(uint32_t off) {
    return off ^ ((off >> 3) & 0x70);
}
__device__ __forceinline__ void sts_h2(uint32_t addr, float lo, float hi) {
    __half2 v = __halves2half2(__float2half_rn(lo), __float2half_rn(hi));
    uint32_t u = *reinterpret_cast<uint32_t*>(&v);
    asm volatile("st.shared.b32 [%0], %1;" :: "r"(addr), "r"(u) : "memory");
}
__device__ __forceinline__ float gelu_exact(float v) {
    return 0.5f * v * (1.0f + erff(v * 0.7071067811865476f));
}

static constexpr int TILE_B = 16384;

// Load one K64 tile into smem, swizzled. 256 threads.
__device__ __forceinline__ void load_tile(uint32_t dst, const char* src,
                                          size_t pitch, int tid) {
    #pragma unroll
    for (int i = 0; i < 4; ++i) {
        int l = tid + (i << 8);
        int r = l >> 3, ch = l & 7;
        uint32_t off = (uint32_t)(r * 128 + ch * 16);
        cp16(dst + swz(off), src + (size_t)r * pitch + ch * 16);
    }
}
// Same, 512 threads.
__device__ __forceinline__ void load_tile512(uint32_t dst, const char* src,
                                             size_t pitch, int tid) {
    #pragma unroll
    for (int i = 0; i < 2; ++i) {
        int l = tid + (i << 9);
        int r = l >> 3, ch = l & 7;
        uint32_t off = (uint32_t)(r * 128 + ch * 16);
        cp16(dst + swz(off), src + (size_t)r * pitch + ch * 16);
    }
}

// One K64 compute step, 64-wide warp tile (acc[2][8][4]).
__device__ __forceinline__ void k64_compute(uint32_t bA, uint32_t bB,
        int a_row, int a_kc, int b_row, int b_kc, float acc[2][8][4]) {
    #pragma unroll
    for (int ks = 0; ks < 4; ++ks) {
        uint32_t ar[2][4], bb[4][4];
        #pragma unroll
        for (int mt = 0; mt < 2; ++mt) {
            uint32_t off = swz((uint32_t)((a_row + mt * 16) * 128
                                          + (a_kc + 2 * ks) * 16));
            ldsm_x4(bA + off, ar[mt]);
        }
        #pragma unroll
        for (int nt = 0; nt < 4; ++nt) {
            uint32_t off = swz((uint32_t)((b_row + nt * 16) * 128
                                          + (b_kc + 2 * ks) * 16));
            ldsm_x4(bB + off, bb[nt]);
        }
        #pragma unroll
        for (int mt = 0; mt < 2; ++mt)
            #pragma unroll
            for (int nt = 0; nt < 8; ++nt)
                mma16816(acc[mt][nt], ar[mt], &bb[nt >> 1][(nt & 1) * 2]);
    }
}
// One K64 compute step, 32-wide warp tile (acc[2][4][4]).
__device__ __forceinline__ void k64_compute32(uint32_t bA, uint32_t bB,
        int a_row, int a_kc, int b_row, int b_kc, float acc[2][4][4]) {
    #pragma unroll
    for (int ks = 0; ks < 4; ++ks) {
        uint32_t ar[2][4], bb[2][4];
        #pragma unroll
        for (int mt = 0; mt < 2; ++mt) {
            uint32_t off = swz((uint32_t)((a_row + mt * 16) * 128
                                          + (a_kc + 2 * ks) * 16));
            ldsm_x4(bA + off, ar[mt]);
        }
        #pragma unroll
        for (int nt = 0; nt < 2; ++nt) {
            uint32_t off = swz((uint32_t)((b_row + nt * 16) * 128
                                          + (b_kc + 2 * ks) * 16));
            ldsm_x4(bB + off, bb[nt]);
        }
        #pragma unroll
        for (int mt = 0; mt < 2; ++mt)
            #pragma unroll
            for (int nt = 0; nt < 4; ++nt)
                mma16816(acc[mt][nt], ar[mt], &bb[nt >> 1][(nt & 1) * 2]);
    }
}

#define LANE_IDX(wid, lane)                                        \
    const int wm = (wid) & 3, wn = (wid) >> 2;                     \
    const int a_row = wm * 32 + ((lane) & 15);                     \
    const int a_kc  = ((lane) >> 4);                               \
    const int b_row = wn * 64 + ((lane) & 7) + (((lane) >> 4) & 1) * 8; \
    const int b_kc  = (((lane) >> 3) & 1);

// Streamed mainloop (256 thr, 8 warps).
template<int KITERS, int STAGES>
__device__ __forceinline__ void gemm128_mainloop(
        uint32_t sb, int tid, int wid, int lane,
        const char* sA, const char* sB, size_t pitch, float acc[2][8][4]) {
    LANE_IDX(wid, lane);
    auto load_stage = [&](int stage, int kt) {
        load_tile(sb + (uint32_t)(stage * 2 + 0) * TILE_B, sA + (size_t)kt * 128, pitch, tid);
        load_tile(sb + (uint32_t)(stage * 2 + 1) * TILE_B, sB + (size_t)kt * 128, pitch, tid);
    };
    #pragma unroll
    for (int s = 0; s < STAGES - 1 && s < KITERS; ++s) {
        load_stage(s, s);
        CP_COMMIT();
    }
    for (int it = 0; it < KITERS; ++it) {
        cp_wait<STAGES - 2>();
        __syncthreads();
        if (it + STAGES - 1 < KITERS)
            load_stage((it + STAGES - 1) % STAGES, it + STAGES - 1);
        CP_COMMIT();
        const int buf = it % STAGES;
        k64_compute(sb + (uint32_t)(buf * 2 + 0) * TILE_B,
                    sb + (uint32_t)(buf * 2 + 1) * TILE_B,
                    a_row, a_kc, b_row, b_kc, acc);
    }
}

template<int KIT>
__device__ __forceinline__ void gemm_smem(uint32_t aBase, uint32_t bBase,
        int wid, int lane, float acc[2][8][4]) {
    LANE_IDX(wid, lane);
    #pragma unroll
    for (int it = 0; it < KIT; ++it)
        k64_compute(aBase + (uint32_t)it * TILE_B, bBase + (uint32_t)it * TILE_B,
                    a_row, a_kc, b_row, b_kc, acc);
}

#define ACC_INIT(acc)                                  \
    _Pragma("unroll")                                  \
    for (int mt = 0; mt < 2; ++mt)                     \
        _Pragma("unroll")                              \
        for (int nt = 0; nt < 8; ++nt)                 \
            _Pragma("unroll")                          \
            for (int q = 0; q < 4; ++q) acc[mt][nt][q] = 0.f;

#define ACC_INIT32(acc)                                \
    _Pragma("unroll")                                  \
    for (int mt = 0; mt < 2; ++mt)                     \
        _Pragma("unroll")                              \
        for (int nt = 0; nt < 4; ++nt)                 \
            _Pragma("unroll")                          \
            for (int q = 0; q < 4; ++q) acc[mt][nt][q] = 0.f;

// ---------------------------------------------------------------------------
// COMBINED LN1 + weight prep (one launch) — R14 proven
// ---------------------------------------------------------------------------
__global__ void k_ln1_prep(const float* __restrict__ x,
                           const float* __restrict__ g1,
                           const float* __restrict__ b1,
                           __half* __restrict__ xt,
                           __half* __restrict__ xn,
                           const float* __restrict__ sed_w,
                           const float* __restrict__ w_proj,
                           const float* __restrict__ w1,
                           const float* __restrict__ w2,
                           __half* __restrict__ bt, __half* __restrict__ bp,
                           __half* __restrict__ bw1, __half* __restrict__ bw2) {
    __shared__ __align__(16) char shraw[128 * 130 * 2];
    const int blk = blockIdx.x;
    const int tid = threadIdx.x;

    if (blk < 4096) {
        float (*sh)[33]  = (float(*)[33])shraw;
        float (*red)[8][32] = (float(*)[8][32])(shraw + 16896);
        float* smean = (float*)(shraw + 18944);
        float* srstd = (float*)(shraw + 19072);

        const int b  = blk >> 9;
        const int s0 = (blk & 511) * 32;
        const int tp = tid & 31;
        const int ty = tid >> 5;

        const float* xb = x + (size_t)b * 128 * 16384 + s0;
        float sum = 0.f, sq = 0.f;
        #pragma unroll
        for (int c0 = 0; c0 < 128; c0 += 8) {
            int c = c0 + ty;
            float v = xb[(size_t)c * 16384 + tp];
            sh[c][tp] = v;
            sum += v; sq += v * v;
        }
        red[0][ty][tp] = sum; red[1][ty][tp] = sq;
        __syncthreads();
        if (ty == 0) {
            float s = 0.f, q = 0.f;
            #pragma unroll
            for (int y = 0; y < 8; ++y) { s += red[0][y][tp]; q += red[1][y][tp]; }
            float m = s * (1.0f / 128.0f);
            smean[tp] = m;
            srstd[tp] = rsqrtf(q * (1.0f / 128.0f) - m * m + 1e-5f);
        }
        __syncthreads();

        #pragma unroll
        for (int li = 0; li < 8; ++li) {
            int l = tid + (li << 8);
            int p = l >> 6, c = (l & 63) * 2;
            int s = s0 + p;
            int hh = s >> 7, ww = s & 127;
            int row = ((((b * 32 + (hh >> 2)) * 32 + (ww >> 2)) << 4)
                      + ((hh & 3) << 2) + (ww & 3));
            float v0 = sh[c][p], v1 = sh[c + 1][p];
            float m = smean[p], rs = srstd[p];
            size_t idx = (size_t)row * 128 + c;
            *(__half2*)(xt + idx) =
                __halves2half2(__float2half_rn(v0), __float2half_rn(v1));
            float n0 = (v0 - m) * rs * g1[c] + b1[c];
            float n1 = (v1 - m) * rs * g1[c + 1] + b1[c + 1];
            *(__half2*)(xn + idx) =
                __halves2half2(__float2half_rn(n0), __float2half_rn(n1));
        }
    } else if (blk < 4352) {
        __half (*tile)[130] = (__half(*)[130])shraw;
        const int bi = blk - 4096;
        const int i = bi >> 4, nblk = bi & 15;
        const int j = i ^ nblk;
        const float s = (float)c_SGN.v[i][j];
        const float* src = sed_w + (size_t)j * 16384;
        for (int idx = tid; idx < 16384; idx += 256) {
            int c = idx >> 7, d = idx & 127;
            tile[c][d] = __float2half_rn(s * __ldg(&src[c * 128 + d]));
        }
        __syncthreads();
        #pragma unroll
        for (int li = 0; li < 32; ++li) {
            int idx = tid + (li << 8);
            int d = idx >> 6, c = (idx & 63) * 2;
            __half2 v = __halves2half2(tile[c][d], tile[c + 1][d]);
            *(__half2*)(bt + (size_t)(nblk * 128 + d) * 2048 + i * 128 + c) = v;
        }
    } else if (blk < 4480) {
        int n = blk - 4352;
        for (int k = tid; k < 128; k += 256)
            bp[(size_t)n * 128 + k] = __float2half_rn(__ldg(&w_proj[(size_t)k * 128 + n]));
    } else if (blk < 4992) {
        int n = blk - 4480;
        for (int k = tid; k < 128; k += 256)
            bw1[(size_t)n * 128 + k] = __float2half_rn(__ldg(&w1[(size_t)k * 512 + n]));
    } else {
        int n = blk - 4992;
        for (int k = tid; k < 512; k += 256)
            bw2[(size_t)n * 512 + k] = __float2half_rn(__ldg(&w2[(size_t)k * 128 + n]));
    }
}

// ---------------------------------------------------------------------------
// FUSED SED + proj + LN2 (R14 proven)
// ---------------------------------------------------------------------------
static constexpr int SED_SMEM = 3 * 2 * TILE_B;

__global__ void __launch_bounds__(256, 2)
k_sedproj(const __half* __restrict__ A, const __half* __restrict__ B,
          const __half* __restrict__ bp,
          const float* __restrict__ bias, const __half* __restrict__ xt,
          const float* __restrict__ g2, const float* __restrict__ b2,
          __half* __restrict__ y, __half* __restrict__ yn) {
    extern __shared__ __align__(1024) char smem[];
    const uint32_t sb = smem_u32(smem);
    const int tid = threadIdx.x, wid = tid >> 5, lane = tid & 31;
    const int wm = wid & 3, wn = wid >> 2;
    const int mrow0 = blockIdx.y * 128;
    const int n0    = blockIdx.x * 128;

    float acc[2][8][4];
    ACC_INIT(acc);

    gemm128_mainloop<32, 3>(sb, tid, wid, lane,
        (const char*)A + (size_t)mrow0 * 4096,
        (const char*)B + (size_t)n0 * 4096, 4096, acc);
    __syncthreads();

    #pragma unroll
    for (int mt = 0; mt < 2; ++mt) {
        const int rl0 = wm * 32 + mt * 16 + (lane >> 2);
        #pragma unroll
        for (int nt = 0; nt < 8; ++nt) {
            const int col = wn * 64 + nt * 8 + (lane & 3) * 2;
            float v0 = gelu_exact(acc[mt][nt][0]);
            float v1 = gelu_exact(acc[mt][nt][1]);
            float v2 = gelu_exact(acc[mt][nt][2]);
            float v3 = gelu_exact(acc[mt][nt][3]);
            uint32_t t = sb + (uint32_t)(col >> 6) * TILE_B;
            sts_h2(t + swz((uint32_t)(rl0 * 128 + (col & 63) * 2)), v0, v1);
            sts_h2(t + swz((uint32_t)((rl0 + 8) * 128 + (col & 63) * 2)), v2, v3);
        }
    }
    load_tile(sb + 2 * TILE_B, (const char*)bp, 256, tid);
    load_tile(sb + 3 * TILE_B, (const char*)bp + 128, 256, tid);
    CP_COMMIT();
    cp_wait<0>();
    __syncthreads();

    float acc2[2][8][4];
    ACC_INIT(acc2);
    gemm_smem<2>(sb, sb + 2 * TILE_B, wid, lane, acc2);

    float s_loc[2][2] = {{0.f,0.f},{0.f,0.f}};
    float q_loc[2][2] = {{0.f,0.f},{0.f,0.f}};
    #pragma unroll
    for (int mt = 0; mt < 2; ++mt) {
        const int rl = wm * 32 + mt * 16 + (lane >> 2);
        #pragma unroll
        for (int nt = 0; nt < 8; ++nt) {
            const int col = wn * 64 + nt * 8 + (lane & 3) * 2;
            float bb0 = __ldg(&bias[col]), bb1 = __ldg(&bias[col + 1]);
            const size_t p0 = (size_t)((mrow0 + rl) * 16 + blockIdx.x) * 128 + col;
            const size_t p1 = (size_t)((mrow0 + rl + 8) * 16 + blockIdx.x) * 128 + col;
            float2 a0 = __half22float2(*(const __half2*)(xt + p0));
            float2 a1 = __half22float2(*(const __half2*)(xt + p1));
            float v0 = acc2[mt][nt][0] + bb0 + a0.x;
            float v1 = acc2[mt][nt][1] + bb1 + a0.y;
            float v2 = acc2[mt][nt][2] + bb0 + a1.x;
            float v3 = acc2[mt][nt][3] + bb1 + a1.y;
            *(__half2*)(y + p0) =
                __halves2half2(__float2half_rn(v0), __float2half_rn(v1));
            *(__half2*)(y + p1) =
                __halves2half2(__float2half_rn(v2), __float2half_rn(v3));
            acc2[mt][nt][0] = v0; acc2[mt][nt][1] = v1;
            acc2[mt][nt][2] = v2; acc2[mt][nt][3] = v3;
            s_loc[mt][0] += v0 + v1; q_loc[mt][0] += v0 * v0 + v1 * v1;
            s_loc[mt][1] += v2 + v3; q_loc[mt][1] += v2 * v2 + v3 * v3;
        }
    }
    #pragma unroll
    for (int mt = 0; mt < 2; ++mt)
        #pragma unroll
        for (int h = 0; h < 2; ++h) {
            float s = s_loc[mt][h], q = q_loc[mt][h];
            s += __shfl_xor_sync(0xffffffffu, s, 1);
            s += __shfl_xor_sync(0xffffffffu, s, 2);
            q += __shfl_xor_sync(0xffffffffu, q, 1);
            q += __shfl_xor_sync(0xffffffffu, q, 2);
            s_loc[mt][h] = s; q_loc[mt][h] = q;
        }
    float* rsum = (float*)(smem + 4 * TILE_B);
    float* rsq  = rsum + 256;
    __syncthreads();
    if ((lane & 3) == 0) {
        #pragma unroll
        for (int mt = 0; mt < 2; ++mt)
            #pragma unroll
            for (int h = 0; h < 2; ++h) {
                int rl = wm * 32 + mt * 16 + h * 8 + (lane >> 2);
                rsum[rl * 2 + wn] = s_loc[mt][h];
                rsq [rl * 2 + wn] = q_loc[mt][h];
            }
    }
    __syncthreads();

    #pragma unroll
    for (int mt = 0; mt < 2; ++mt) {
        const int rl0 = wm * 32 + mt * 16 + (lane >> 2);
        const int rl1 = rl0 + 8;
        float S0 = rsum[rl0 * 2] + rsum[rl0 * 2 + 1];
        float Q0 = rsq [rl0 * 2] + rsq [rl0 * 2 + 1];
        float S1 = rsum[rl1 * 2] + rsum[rl1 * 2 + 1];
        float Q1 = rsq [rl1 * 2] + rsq [rl1 * 2 + 1];
        float mu0 = S0 * (1.0f / 128.0f);
        float rs0 = rsqrtf(Q0 * (1.0f / 128.0f) - mu0 * mu0 + 1e-5f);
        float mu1 = S1 * (1.0f / 128.0f);
        float rs1 = rsqrtf(Q1 * (1.0f / 128.0f) - mu1 * mu1 + 1e-5f);
        #pragma unroll
        for (int nt = 0; nt < 8; ++nt) {
            const int col = wn * 64 + nt * 8 + (lane & 3) * 2;
            float g0 = __ldg(&g2[col]), g1 = __ldg(&g2[col + 1]);
            float be0 = __ldg(&b2[col]), be1 = __ldg(&b2[col + 1]);
            float n0 = (acc2[mt][nt][0] - mu0) * rs0 * g0 + be0;
            float n1 = (acc2[mt][nt][1] - mu0) * rs0 * g1 + be1;
            float n2 = (acc2[mt][nt][2] - mu1) * rs1 * g0 + be0;
            float n3 = (acc2[mt][nt][3] - mu1) * rs1 * g1 + be1;
            const size_t p0 = (size_t)((mrow0 + rl0) * 16 + blockIdx.x) * 128 + col;
            const size_t p1 = (size_t)((mrow0 + rl1) * 16 + blockIdx.x) * 128 + col;
            *(__half2*)(yn + p0) =
                __halves2half2(__float2half_rn(n0), __float2half_rn(n1));
            *(__half2*)(yn + p1) =
                __halves2half2(__float2half_rn(n2), __float2half_rn(n3));
        }
    }
}

// ---------------------------------------------------------------------------
// FUSED MLP v2 — cross-chunk software pipeline: phase(c) computes
// GEMM2(c) and GEMM1(c+1) as interleaved independent MMA chains.
// smem: yn 0-1 | h0 2-3 | h1 4-5 | w1 buf0 6-7 buf1 8-9 | w2 buf0 10-11
//       buf1 12-13  = 14 tiles = 224 KB
// ---------------------------------------------------------------------------
static constexpr int MLP_SMEM = 14 * TILE_B;   // 229376

__global__ void __launch_bounds__(512, 1)
k_mlp(const __half* __restrict__ yn,
      const __half* __restrict__ bw1, const __half* __restrict__ bw2,
      const float* __restrict__ b1v, const float* __restrict__ b2v,
      const __half* __restrict__ y, float* __restrict__ out) {
    extern __shared__ __align__(1024) char smem[];
    const uint32_t sb = smem_u32(smem);
    const int tid = threadIdx.x, wid = tid >> 5, lane = tid & 31;
    const int wm = wid & 3, wn = wid >> 2;
    const int mrow0 = blockIdx.x * 128;

    const int a_row = wm * 32 + (lane & 15);
    const int a_kc  = lane >> 4;
    const int b_row = wn * 32 + (lane & 7) + ((lane >> 4) & 1) * 8;
    const int b_kc  = (lane >> 3) & 1;

    const uint32_t T_YN = sb;
    const uint32_t T_H  = sb + 2 * TILE_B;     // + buf*2*TILE_B
    const uint32_t T_W1 = sb + 6 * TILE_B;     // + buf*2*TILE_B
    const uint32_t T_W2 = sb + 10 * TILE_B;    // + buf*2*TILE_B

    // ---- prologue loads ----
    load_tile512(T_YN,          (const char*)yn + (size_t)mrow0 * 256, 256, tid);
    load_tile512(T_YN + TILE_B, (const char*)yn + (size_t)mrow0 * 256 + 128, 256, tid);
    load_tile512(T_W1,              (const char*)bw1, 256, tid);
    load_tile512(T_W1 + TILE_B,     (const char*)bw1 + 128, 256, tid);
    load_tile512(T_W1 + 2 * TILE_B, (const char*)bw1 + 256 * 128, 256, tid);
    load_tile512(T_W1 + 3 * TILE_B, (const char*)bw1 + 256 * 128 + 128, 256, tid);
    load_tile512(T_W2,              (const char*)bw2, 1024, tid);
    load_tile512(T_W2 + TILE_B,     (const char*)bw2 + 128, 1024, tid);
    CP_COMMIT();
    load_tile512(T_W2 + 2 * TILE_B, (const char*)bw2 + 256, 1024, tid);
    load_tile512(T_W2 + 3 * TILE_B, (const char*)bw2 + 256 + 128, 1024, tid);
    CP_COMMIT();
    cp_wait<1>();           // first commit (yn, w1(0), w1(1), w2(0)) resident
    __syncthreads();

    // ---- GEMM1(0) -> h0 ----
    float acc2[2][4][4];
    ACC_INIT32(acc2);
    {
        float acc1[2][4][4];
        ACC_INIT32(acc1);
        #pragma unroll
        for (int it = 0; it < 2; ++it)
            k64_compute32(T_YN + (uint32_t)it * TILE_B,
                          T_W1 + (uint32_t)it * TILE_B,
                          a_row, a_kc, b_row, b_kc, acc1);
        #pragma unroll
        for (int mt = 0; mt < 2; ++mt) {
            const int rl0 = wm * 32 + mt * 16 + (lane >> 2);
            #pragma unroll
            for (int nt = 0; nt < 4; ++nt) {
                const int col = wn * 32 + nt * 8 + (lane & 3) * 2;
                float bb0 = __ldg(&b1v[col]);
                float bb1 = __ldg(&b1v[col + 1]);
                float v0 = gelu_exact(acc1[mt][nt][0] + bb0);
                float v1 = gelu_exact(acc1[mt][nt][1] + bb1);
                float v2 = gelu_exact(acc1[mt][nt][2] + bb0);
                float v3 = gelu_exact(acc1[mt][nt][3] + bb1);
                uint32_t t = T_H + (uint32_t)(col >> 6) * TILE_B;
                sts_h2(t + swz((uint32_t)(rl0 * 128 + (col & 63) * 2)), v0, v1);
                sts_h2(t + swz((uint32_t)((rl0 + 8) * 128 + (col & 63) * 2)), v2, v3);
            }
        }
    }

    // ---- pipelined phases: GEMM2(c) || GEMM1(c+1) ----
    #pragma unroll
    for (int c = 0; c < 4; ++c) {
        // pre-prefetch w1(c+2) into W1[c&1]  (buffer free: GEMM1(c+1-...)=w1(c) last read in prior phase)
        if (c + 2 < 4) {
            uint32_t d = T_W1 + (uint32_t)(c & 1) * 2 * TILE_B;
            load_tile512(d,          (const char*)bw1 + (size_t)(c + 2) * 256 * 128, 256, tid);
            load_tile512(d + TILE_B, (const char*)bw1 + (size_t)(c + 2) * 256 * 128 + 128, 256, tid);
        }
        CP_COMMIT();
        cp_wait<1>();        // everything except this phase's pre-prefetch resident
        __syncthreads();     // h[(c)&1] stores + prior reads visible/done

        const uint32_t hb  = T_H  + (uint32_t)(c & 1) * 2 * TILE_B;
        const uint32_t w2b = T_W2 + (uint32_t)(c & 1) * 2 * TILE_B;
        const uint32_t w1b = T_W1 + (uint32_t)((c + 1) & 1) * 2 * TILE_B;

        float acc1[2][4][4];
        ACC_INIT32(acc1);
        if (c < 3) {
            // interleaved dual chains
            #pragma unroll
            for (int it = 0; it < 2; ++it) {
                k64_compute32(hb + (uint32_t)it * TILE_B,
                              w2b + (uint32_t)it * TILE_B,
                              a_row, a_kc, b_row, b_kc, acc2);
                k64_compute32(T_YN + (uint32_t)it * TILE_B,
                              w1b + (uint32_t)it * TILE_B,
                              a_row, a_kc, b_row, b_kc, acc1);
            }
        } else {
            #pragma unroll
            for (int it = 0; it < 2; ++it)
                k64_compute32(hb + (uint32_t)it * TILE_B,
                              w2b + (uint32_t)it * TILE_B,
                              a_row, a_kc, b_row, b_kc, acc2);
        }
        __syncthreads();     // all reads of h[c&1], w2[c&1], w1[(c+1)&1] done

        if (c < 3) {
            // store h(c+1) into buffer (c+1)&1
            const uint32_t hn = T_H + (uint32_t)((c + 1) & 1) * 2 * TILE_B;
            #pragma unroll
            for (int mt = 0; mt < 2; ++mt) {
                const int rl0 = wm * 32 + mt * 16 + (lane >> 2);
                #pragma unroll
                for (int nt = 0; nt < 4; ++nt) {
                    const int col = wn * 32 + nt * 8 + (lane & 3) * 2;
                    float bb0 = __ldg(&b1v[(c + 1) * 128 + col]);
                    float bb1 = __ldg(&b1v[(c + 1) * 128 + col + 1]);
                    float v0 = gelu_exact(acc1[mt][nt][0] + bb0);
                    float v1 = gelu_exact(acc1[mt][nt][1] + bb1);
                    float v2 = gelu_exact(acc1[mt][nt][2] + bb0);
                    float v3 = gelu_exact(acc1[mt][nt][3] + bb1);
                    uint32_t t = hn + (uint32_t)(col >> 6) * TILE_B;
                    sts_h2(t + swz((uint32_t)(rl0 * 128 + (col & 63) * 2)), v0, v1);
                    sts_h2(t + swz((uint32_t)((rl0 + 8) * 128 + (col & 63) * 2)), v2, v3);
                }
            }
        }
        // post-prefetch w2(c+2) into W2[c&1] (reads done at the sync above)
        if (c + 2 < 4) {
            uint32_t d = T_W2 + (uint32_t)(c & 1) * 2 * TILE_B;
            load_tile512(d,          (const char*)bw2 + (size_t)(c + 2) * 256, 1024, tid);
            load_tile512(d + TILE_B, (const char*)bw2 + (size_t)(c + 2) * 256 + 128, 1024, tid);
        }
        CP_COMMIT();
    }
    cp_wait<0>();
    __syncthreads();

    // ---- final: b2 + y residual -> staged NCHW writeout ----
    float* stg = (float*)smem;
    #pragma unroll
    for (int mt = 0; mt < 2; ++mt) {
        const int rl = wm * 32 + mt * 16 + (lane >> 2);
        #pragma unroll
        for (int nt = 0; nt < 4; ++nt) {
            const int col = wn * 32 + nt * 8 + (lane & 3) * 2;
            float bb0 = __ldg(&b2v[col]), bb1 = __ldg(&b2v[col + 1]);
            const size_t o0 = (size_t)(mrow0 + rl) * 128 + col;
            const size_t o1 = (size_t)(mrow0 + rl + 8) * 128 + col;
            float2 a0 = __half22float2(*(const __half2*)(y + o0));
            float2 a1 = __half22float2(*(const __half2*)(y + o1));
            stg[rl * 132 + col]           = acc2[mt][nt][0] + bb0 + a0.x;
            stg[rl * 132 + col + 1]       = acc2[mt][nt][1] + bb1 + a0.y;
            stg[(rl + 8) * 132 + col]     = acc2[mt][nt][2] + bb0 + a1.x;
            stg[(rl + 8) * 132 + col + 1] = acc2[mt][nt][3] + bb1 + a1.y;
        }
    }
    __syncthreads();

    const int widx0 = blockIdx.x * 8;
    const int b   = widx0 >> 10;
    const int h4  = (widx0 >> 5) & 31;
    const int w40 = widx0 & 31;
    for (int seg = wid; seg < 512; seg += 16) {
        int ch = seg >> 2, hh = seg & 3;
        int row = ((lane >> 2) << 4) + (hh << 2) + (lane & 3);
        float val = stg[row * 132 + ch];
        out[(((size_t)(b * 128 + ch)) * 128 + h4 * 4 + hh) * 128
            + w40 * 4 + lane] = val;
    }
}

// ---------------------------------------------------------------------------
// Launch
// ---------------------------------------------------------------------------
extern "C" void kernel_launch(void* const* d_in, const int* in_sizes, int n_in,
                              void* d_out, int out_size) {
    const float* x      = (const float*)d_in[0];
    const float* gamma1 = (const float*)d_in[1];
    const float* beta1  = (const float*)d_in[2];
    const float* sed_w  = (const float*)d_in[3];
    const float* w_proj = (const float*)d_in[4];
    const float* b_proj = (const float*)d_in[5];
    const float* gamma2 = (const float*)d_in[6];
    const float* beta2  = (const float*)d_in[7];
    const float* w1     = (const float*)d_in[8];
    const float* b1     = (const float*)d_in[9];
    const float* w2     = (const float*)d_in[10];
    const float* b2     = (const float*)d_in[11];
    float* out = (float*)d_out;

    __half *xt, *y, *xn, *yn, *bt, *bp, *bw1, *bw2;
    cudaGetSymbolAddress((void**)&xt, g_xt);
    cudaGetSymbolAddress((void**)&y,  g_y);
    cudaGetSymbolAddress((void**)&xn, g_xn);
    cudaGetSymbolAddress((void**)&yn, g_yn);
    cudaGetSymbolAddress((void**)&bt, g_bt);
    cudaGetSymbolAddress((void**)&bp, g_bp);
    cudaGetSymbolAddress((void**)&bw1, g_b1);
    cudaGetSymbolAddress((void**)&bw2, g_b2);

    cudaFuncSetAttribute(k_sedproj, cudaFuncAttributeMaxDynamicSharedMemorySize, SED_SMEM);
    cudaFuncSetAttribute(k_mlp,     cudaFuncAttributeMaxDynamicSharedMemorySize, MLP_SMEM);

    // 1) LN1 + transpose + all weight preps
    k_ln1_prep<<<5120, 256>>>(x, gamma1, beta1, xt, xn,
                              sed_w, w_proj, w1, w2, bt, bp, bw1, bw2);

    // 2) SED + gelu + proj + residual + LN2 (fused)
    k_sedproj<<<dim3(16, 64), 256, SED_SMEM>>>(
        xn, bt, bp, b_proj, xt, gamma2, beta2, y, yn);

    // 3) MLP (fused, cross-chunk pipelined)
    k_mlp<<<1024, 512, MLP_SMEM>>>(yn, bw1, bw2, b1, b2, y, out);
}

// round 16
// speedup vs baseline: 1.0058x; 1.0058x over previous
#include <cuda_runtime.h>
#include <cuda_fp16.h>
#include <cstdint>
#include <cstddef>

// ---------------------------------------------------------------------------
// Cayley-Dickson sign table:  e_i * e_j = sign(i,j) * e_{i XOR j}
// ---------------------------------------------------------------------------
constexpr int cdsign(int i, int j, int n) {
    return (n == 1) ? 1
         : (i < n/2 && j < n/2) ? cdsign(i, j, n/2)
         : (i < n/2)            ? cdsign(j - n/2, i, n/2)
         : (j < n/2)            ? cdsign(i - n/2, j, n/2) * (j == 0 ? 1 : -1)
         : -cdsign(j - n/2, i - n/2, n/2) * ((j - n/2) == 0 ? 1 : -1);
}
struct SgnTab { signed char v[16][16]; };
constexpr SgnTab make_sgn() {
    SgnTab t{};
    for (int i = 0; i < 16; ++i)
        for (int j = 0; j < 16; ++j)
            t.v[i][j] = (signed char)cdsign(i, j, 16);
    return t;
}
__constant__ SgnTab c_SGN = make_sgn();

// ---------------------------------------------------------------------------
static constexpr int C = 128, NPIX = 8 * 128 * 128;   // 131072

// residual buffers fp16 (calibrated error budget)
__device__ __align__(256) __half g_xt[NPIX * C];
__device__ __align__(256) __half g_y [NPIX * C];

// fp16 operand buffers
__device__ __align__(256) __half g_xn[NPIX * C];
__device__ __align__(256) __half g_yn[NPIX * C];
// weight (B^T, n-major rows of K) buffers
__device__ __align__(256) __half g_bt[2048 * 2048];
__device__ __align__(256) __half g_bp[128 * 128];
__device__ __align__(256) __half g_b1[512 * 128];
__device__ __align__(256) __half g_b2[128 * 512];

// ---------------------------------------------------------------------------
// PTX helpers
// ---------------------------------------------------------------------------
__device__ __forceinline__ uint32_t smem_u32(const void* p) {
    uint32_t a;
    asm("{ .reg .u64 t; cvta.to.shared.u64 t, %1; cvt.u32.u64 %0, t; }"
        : "=r"(a) : "l"(p));
    return a;
}
__device__ __forceinline__ void cp16(uint32_t dst, const void* src) {
    asm volatile("cp.async.cg.shared.global [%0], [%1], 16;" :: "r"(dst), "l"(src));
}
#define CP_COMMIT() asm volatile("cp.async.commit_group;" ::: "memory")
template<int N>
__device__ __forceinline__ void cp_wait() {
    asm volatile("cp.async.wait_group %0;" :: "n"(N) : "memory");
}
__device__ __forceinline__ void ldsm_x4(uint32_t addr, uint32_t* r) {
    asm volatile("ldmatrix.sync.aligned.m8n8.x4.shared.b16 {%0,%1,%2,%3}, [%4];"
        : "=r"(r[0]), "=r"(r[1]), "=r"(r[2]), "=r"(r[3]) : "r"(addr));
}
__device__ __forceinline__ void mma16816(float* c, const uint32_t* a, const uint32_t* b) {
    asm volatile("mma.sync.aligned.m16n8k16.row.col.f32.f16.f16.f32 "
        "{%0,%1,%2,%3}, {%4,%5,%6,%7}, {%8,%9}, {%0,%1,%2,%3};"
        : "+f"(c[0]), "+f"(c[1]), "+f"(c[2]), "+f"(c[3])
        : "r"(a[0]), "r"(a[1]), "r"(a[2]), "r"(a[3]), "r"(b[0]), "r"(b[1]));
}
__device__ __forceinline__ uint32_t swz(uint32_t off) {
    return off ^ ((off >> 3) & 0x70);
}
__device__ __forceinline__ void sts_h2(uint32_t addr, float lo, float hi) {
    __half2 v = __halves2half2(__float2half_rn(lo), __float2half_rn(hi));
    uint32_t u = *reinterpret_cast<uint32_t*>(&v);
    asm volatile("st.shared.b32 [%0], %1;" :: "r"(addr), "r"(u) : "memory");
}
__device__ __forceinline__ float gelu_exact(float v) {
    return 0.5f * v * (1.0f + erff(v * 0.7071067811865476f));
}

static constexpr int TILE_B = 16384;

// Load one K64 tile into smem, swizzled. 256 threads.
__device__ __forceinline__ void load_tile(uint32_t dst, const char* src,
                                          size_t pitch, int tid) {
    #pragma unroll
    for (int i = 0; i < 4; ++i) {
        int l = tid + (i << 8);
        int r = l >> 3, ch = l & 7;
        uint32_t off = (uint32_t)(r * 128 + ch * 16);
        cp16(dst + swz(off), src + (size_t)r * pitch + ch * 16);
    }
}
// Same, 512 threads.
__device__ __forceinline__ void load_tile512(uint32_t dst, const char* src,
                                             size_t pitch, int tid) {
    #pragma unroll
    for (int i = 0; i < 2; ++i) {
        int l = tid + (i << 9);
        int r = l >> 3, ch = l & 7;
        uint32_t off = (uint32_t)(r * 128 + ch * 16);
        cp16(dst + swz(off), src + (size_t)r * pitch + ch * 16);
    }
}

// One K64 compute step, 64-wide warp tile (acc[2][8][4]).
__device__ __forceinline__ void k64_compute(uint32_t bA, uint32_t bB,
        int a_row, int a_kc, int b_row, int b_kc, float acc[2][8][4]) {
    #pragma unroll
    for (int ks = 0; ks < 4; ++ks) {
        uint32_t ar[2][4], bb[4][4];
        #pragma unroll
        for (int mt = 0; mt < 2; ++mt) {
            uint32_t off = swz((uint32_t)((a_row + mt * 16) * 128
                                          + (a_kc + 2 * ks) * 16));
            ldsm_x4(bA + off, ar[mt]);
        }
        #pragma unroll
        for (int nt = 0; nt < 4; ++nt) {
            uint32_t off = swz((uint32_t)((b_row + nt * 16) * 128
                                          + (b_kc + 2 * ks) * 16));
            ldsm_x4(bB + off, bb[nt]);
        }
        #pragma unroll
        for (int mt = 0; mt < 2; ++mt)
            #pragma unroll
            for (int nt = 0; nt < 8; ++nt)
                mma16816(acc[mt][nt], ar[mt], &bb[nt >> 1][(nt & 1) * 2]);
    }
}
// One K64 compute step, 32-wide warp tile (acc[2][4][4]).
__device__ __forceinline__ void k64_compute32(uint32_t bA, uint32_t bB,
        int a_row, int a_kc, int b_row, int b_kc, float acc[2][4][4]) {
    #pragma unroll
    for (int ks = 0; ks < 4; ++ks) {
        uint32_t ar[2][4], bb[2][4];
        #pragma unroll
        for (int mt = 0; mt < 2; ++mt) {
            uint32_t off = swz((uint32_t)((a_row + mt * 16) * 128
                                          + (a_kc + 2 * ks) * 16));
            ldsm_x4(bA + off, ar[mt]);
        }
        #pragma unroll
        for (int nt = 0; nt < 2; ++nt) {
            uint32_t off = swz((uint32_t)((b_row + nt * 16) * 128
                                          + (b_kc + 2 * ks) * 16));
            ldsm_x4(bB + off, bb[nt]);
        }
        #pragma unroll
        for (int mt = 0; mt < 2; ++mt)
            #pragma unroll
            for (int nt = 0; nt < 4; ++nt)
                mma16816(acc[mt][nt], ar[mt], &bb[nt >> 1][(nt & 1) * 2]);
    }
}

#define LANE_IDX(wid, lane)                                        \
    const int wm = (wid) & 3, wn = (wid) >> 2;                     \
    const int a_row = wm * 32 + ((lane) & 15);                     \
    const int a_kc  = ((lane) >> 4);                               \
    const int b_row = wn * 64 + ((lane) & 7) + (((lane) >> 4) & 1) * 8; \
    const int b_kc  = (((lane) >> 3) & 1);

// Streamed mainloop (256 thr, 8 warps).
template<int KITERS, int STAGES>
__device__ __forceinline__ void gemm128_mainloop(
        uint32_t sb, int tid, int wid, int lane,
        const char* sA, const char* sB, size_t pitch, float acc[2][8][4]) {
    LANE_IDX(wid, lane);
    auto load_stage = [&](int stage, int kt) {
        load_tile(sb + (uint32_t)(stage * 2 + 0) * TILE_B, sA + (size_t)kt * 128, pitch, tid);
        load_tile(sb + (uint32_t)(stage * 2 + 1) * TILE_B, sB + (size_t)kt * 128, pitch, tid);
    };
    #pragma unroll
    for (int s = 0; s < STAGES - 1 && s < KITERS; ++s) {
        load_stage(s, s);
        CP_COMMIT();
    }
    for (int it = 0; it < KITERS; ++it) {
        cp_wait<STAGES - 2>();
        __syncthreads();
        if (it + STAGES - 1 < KITERS)
            load_stage((it + STAGES - 1) % STAGES, it + STAGES - 1);
        CP_COMMIT();
        const int buf = it % STAGES;
        k64_compute(sb + (uint32_t)(buf * 2 + 0) * TILE_B,
                    sb + (uint32_t)(buf * 2 + 1) * TILE_B,
                    a_row, a_kc, b_row, b_kc, acc);
    }
}

template<int KIT>
__device__ __forceinline__ void gemm_smem(uint32_t aBase, uint32_t bBase,
        int wid, int lane, float acc[2][8][4]) {
    LANE_IDX(wid, lane);
    #pragma unroll
    for (int it = 0; it < KIT; ++it)
        k64_compute(aBase + (uint32_t)it * TILE_B, bBase + (uint32_t)it * TILE_B,
                    a_row, a_kc, b_row, b_kc, acc);
}

#define ACC_INIT(acc)                                  \
    _Pragma("unroll")                                  \
    for (int mt = 0; mt < 2; ++mt)                     \
        _Pragma("unroll")                              \
        for (int nt = 0; nt < 8; ++nt)                 \
            _Pragma("unroll")                          \
            for (int q = 0; q < 4; ++q) acc[mt][nt][q] = 0.f;

#define ACC_INIT32(acc)                                \
    _Pragma("unroll")                                  \
    for (int mt = 0; mt < 2; ++mt)                     \
        _Pragma("unroll")                              \
        for (int nt = 0; nt < 4; ++nt)                 \
            _Pragma("unroll")                          \
            for (int q = 0; q < 4; ++q) acc[mt][nt][q] = 0.f;

// ---------------------------------------------------------------------------
// COMBINED LN1 + weight prep (one launch)
// blocks [0, 4096)    : LN1 + transpose (half2 writeout)
// blocks [4096, 4352) : SED weight prep (coalesced transpose, half2 writes)
// blocks [4352, 4480) : w_proj prep
// blocks [4480, 4992) : w1 prep
// blocks [4992, 5120) : w2 prep
// ---------------------------------------------------------------------------
__global__ void k_ln1_prep(const float* __restrict__ x,
                           const float* __restrict__ g1,
                           const float* __restrict__ b1,
                           __half* __restrict__ xt,
                           __half* __restrict__ xn,
                           const float* __restrict__ sed_w,
                           const float* __restrict__ w_proj,
                           const float* __restrict__ w1,
                           const float* __restrict__ w2,
                           __half* __restrict__ bt, __half* __restrict__ bp,
                           __half* __restrict__ bw1, __half* __restrict__ bw2) {
    __shared__ __align__(16) char shraw[128 * 130 * 2];   // 33280 B, aliased
    const int blk = blockIdx.x;
    const int tid = threadIdx.x;

    if (blk < 4096) {
        // ---------------- LN1 ----------------
        float (*sh)[33]  = (float(*)[33])shraw;
        float (*red)[8][32] = (float(*)[8][32])(shraw + 16896);
        float* smean = (float*)(shraw + 18944);
        float* srstd = (float*)(shraw + 19072);

        const int b  = blk >> 9;
        const int s0 = (blk & 511) * 32;
        const int tp = tid & 31;
        const int ty = tid >> 5;

        const float* xb = x + (size_t)b * 128 * 16384 + s0;
        float sum = 0.f, sq = 0.f;
        #pragma unroll
        for (int c0 = 0; c0 < 128; c0 += 8) {
            int c = c0 + ty;
            float v = xb[(size_t)c * 16384 + tp];
            sh[c][tp] = v;
            sum += v; sq += v * v;
        }
        red[0][ty][tp] = sum; red[1][ty][tp] = sq;
        __syncthreads();
        if (ty == 0) {
            float s = 0.f, q = 0.f;
            #pragma unroll
            for (int y = 0; y < 8; ++y) { s += red[0][y][tp]; q += red[1][y][tp]; }
            float m = s * (1.0f / 128.0f);
            smean[tp] = m;
            srstd[tp] = rsqrtf(q * (1.0f / 128.0f) - m * m + 1e-5f);
        }
        __syncthreads();

        // half2 writeout: 2048 channel-pairs (p = pixel, c = 2*pair)
        #pragma unroll
        for (int li = 0; li < 8; ++li) {
            int l = tid + (li << 8);
            int p = l >> 6, c = (l & 63) * 2;
            int s = s0 + p;
            int hh = s >> 7, ww = s & 127;
            int row = ((((b * 32 + (hh >> 2)) * 32 + (ww >> 2)) << 4)
                      + ((hh & 3) << 2) + (ww & 3));
            float v0 = sh[c][p], v1 = sh[c + 1][p];
            float m = smean[p], rs = srstd[p];
            size_t idx = (size_t)row * 128 + c;
            *(__half2*)(xt + idx) =
                __halves2half2(__float2half_rn(v0), __float2half_rn(v1));
            float n0 = (v0 - m) * rs * g1[c] + b1[c];
            float n1 = (v1 - m) * rs * g1[c + 1] + b1[c + 1];
            *(__half2*)(xn + idx) =
                __halves2half2(__float2half_rn(n0), __float2half_rn(n1));
        }
    } else if (blk < 4352) {
        // ------- SED prep: coalesced transpose, half2 writes -------
        __half (*tile)[130] = (__half(*)[130])shraw;
        const int bi = blk - 4096;
        const int i = bi >> 4, nblk = bi & 15;
        const int j = i ^ nblk;
        const float s = (float)c_SGN.v[i][j];
        const float* src = sed_w + (size_t)j * 16384;
        for (int idx = tid; idx < 16384; idx += 256) {
            int c = idx >> 7, d = idx & 127;
            tile[c][d] = __float2half_rn(s * __ldg(&src[c * 128 + d]));
        }
        __syncthreads();
        // write bt rows (contiguous c), 8192 half2 pairs
        #pragma unroll
        for (int li = 0; li < 32; ++li) {
            int idx = tid + (li << 8);
            int d = idx >> 6, c = (idx & 63) * 2;
            __half2 v = __halves2half2(tile[c][d], tile[c + 1][d]);
            *(__half2*)(bt + (size_t)(nblk * 128 + d) * 2048 + i * 128 + c) = v;
        }
    } else if (blk < 4480) {
        int n = blk - 4352;
        for (int k = tid; k < 128; k += 256)
            bp[(size_t)n * 128 + k] = __float2half_rn(__ldg(&w_proj[(size_t)k * 128 + n]));
    } else if (blk < 4992) {
        int n = blk - 4480;
        for (int k = tid; k < 128; k += 256)
            bw1[(size_t)n * 128 + k] = __float2half_rn(__ldg(&w1[(size_t)k * 512 + n]));
    } else {
        int n = blk - 4992;
        for (int k = tid; k < 512; k += 256)
            bw2[(size_t)n * 512 + k] = __float2half_rn(__ldg(&w2[(size_t)k * 128 + n]));
    }
}

// ---------------------------------------------------------------------------
// FUSED SED + proj + LN2
// ---------------------------------------------------------------------------
static constexpr int SED_SMEM = 3 * 2 * TILE_B;

__global__ void __launch_bounds__(256, 2)
k_sedproj(const __half* __restrict__ A, const __half* __restrict__ B,
          const __half* __restrict__ bp,
          const float* __restrict__ bias, const __half* __restrict__ xt,
          const float* __restrict__ g2, const float* __restrict__ b2,
          __half* __restrict__ y, __half* __restrict__ yn) {
    extern __shared__ __align__(1024) char smem[];
    const uint32_t sb = smem_u32(smem);
    const int tid = threadIdx.x, wid = tid >> 5, lane = tid & 31;
    const int wm = wid & 3, wn = wid >> 2;
    const int mrow0 = blockIdx.y * 128;
    const int n0    = blockIdx.x * 128;

    float acc[2][8][4];
    ACC_INIT(acc);

    gemm128_mainloop<32, 3>(sb, tid, wid, lane,
        (const char*)A + (size_t)mrow0 * 4096,
        (const char*)B + (size_t)n0 * 4096, 4096, acc);
    __syncthreads();

    #pragma unroll
    for (int mt = 0; mt < 2; ++mt) {
        const int rl0 = wm * 32 + mt * 16 + (lane >> 2);
        #pragma unroll
        for (int nt = 0; nt < 8; ++nt) {
            const int col = wn * 64 + nt * 8 + (lane & 3) * 2;
            float v0 = gelu_exact(acc[mt][nt][0]);
            float v1 = gelu_exact(acc[mt][nt][1]);
            float v2 = gelu_exact(acc[mt][nt][2]);
            float v3 = gelu_exact(acc[mt][nt][3]);
            uint32_t t = sb + (uint32_t)(col >> 6) * TILE_B;
            sts_h2(t + swz((uint32_t)(rl0 * 128 + (col & 63) * 2)), v0, v1);
            sts_h2(t + swz((uint32_t)((rl0 + 8) * 128 + (col & 63) * 2)), v2, v3);
        }
    }
    load_tile(sb + 2 * TILE_B, (const char*)bp, 256, tid);
    load_tile(sb + 3 * TILE_B, (const char*)bp + 128, 256, tid);
    CP_COMMIT();
    cp_wait<0>();
    __syncthreads();

    float acc2[2][8][4];
    ACC_INIT(acc2);
    gemm_smem<2>(sb, sb + 2 * TILE_B, wid, lane, acc2);

    float s_loc[2][2] = {{0.f,0.f},{0.f,0.f}};
    float q_loc[2][2] = {{0.f,0.f},{0.f,0.f}};
    #pragma unroll
    for (int mt = 0; mt < 2; ++mt) {
        const int rl = wm * 32 + mt * 16 + (lane >> 2);
        #pragma unroll
        for (int nt = 0; nt < 8; ++nt) {
            const int col = wn * 64 + nt * 8 + (lane & 3) * 2;
            float bb0 = __ldg(&bias[col]), bb1 = __ldg(&bias[col + 1]);
            const size_t p0 = (size_t)((mrow0 + rl) * 16 + blockIdx.x) * 128 + col;
            const size_t p1 = (size_t)((mrow0 + rl + 8) * 16 + blockIdx.x) * 128 + col;
            float2 a0 = __half22float2(*(const __half2*)(xt + p0));
            float2 a1 = __half22float2(*(const __half2*)(xt + p1));
            float v0 = acc2[mt][nt][0] + bb0 + a0.x;
            float v1 = acc2[mt][nt][1] + bb1 + a0.y;
            float v2 = acc2[mt][nt][2] + bb0 + a1.x;
            float v3 = acc2[mt][nt][3] + bb1 + a1.y;
            *(__half2*)(y + p0) =
                __halves2half2(__float2half_rn(v0), __float2half_rn(v1));
            *(__half2*)(y + p1) =
                __halves2half2(__float2half_rn(v2), __float2half_rn(v3));
            acc2[mt][nt][0] = v0; acc2[mt][nt][1] = v1;
            acc2[mt][nt][2] = v2; acc2[mt][nt][3] = v3;
            s_loc[mt][0] += v0 + v1; q_loc[mt][0] += v0 * v0 + v1 * v1;
            s_loc[mt][1] += v2 + v3; q_loc[mt][1] += v2 * v2 + v3 * v3;
        }
    }
    #pragma unroll
    for (int mt = 0; mt < 2; ++mt)
        #pragma unroll
        for (int h = 0; h < 2; ++h) {
            float s = s_loc[mt][h], q = q_loc[mt][h];
            s += __shfl_xor_sync(0xffffffffu, s, 1);
            s += __shfl_xor_sync(0xffffffffu, s, 2);
            q += __shfl_xor_sync(0xffffffffu, q, 1);
            q += __shfl_xor_sync(0xffffffffu, q, 2);
            s_loc[mt][h] = s; q_loc[mt][h] = q;
        }
    float* rsum = (float*)(smem + 4 * TILE_B);
    float* rsq  = rsum + 256;
    __syncthreads();
    if ((lane & 3) == 0) {
        #pragma unroll
        for (int mt = 0; mt < 2; ++mt)
            #pragma unroll
            for (int h = 0; h < 2; ++h) {
                int rl = wm * 32 + mt * 16 + h * 8 + (lane >> 2);
                rsum[rl * 2 + wn] = s_loc[mt][h];
                rsq [rl * 2 + wn] = q_loc[mt][h];
            }
    }
    __syncthreads();

    #pragma unroll
    for (int mt = 0; mt < 2; ++mt) {
        const int rl0 = wm * 32 + mt * 16 + (lane >> 2);
        const int rl1 = rl0 + 8;
        float S0 = rsum[rl0 * 2] + rsum[rl0 * 2 + 1];
        float Q0 = rsq [rl0 * 2] + rsq [rl0 * 2 + 1];
        float S1 = rsum[rl1 * 2] + rsum[rl1 * 2 + 1];
        float Q1 = rsq [rl1 * 2] + rsq [rl1 * 2 + 1];
        float mu0 = S0 * (1.0f / 128.0f);
        float rs0 = rsqrtf(Q0 * (1.0f / 128.0f) - mu0 * mu0 + 1e-5f);
        float mu1 = S1 * (1.0f / 128.0f);
        float rs1 = rsqrtf(Q1 * (1.0f / 128.0f) - mu1 * mu1 + 1e-5f);
        #pragma unroll
        for (int nt = 0; nt < 8; ++nt) {
            const int col = wn * 64 + nt * 8 + (lane & 3) * 2;
            float g0 = __ldg(&g2[col]), g1 = __ldg(&g2[col + 1]);
            float be0 = __ldg(&b2[col]), be1 = __ldg(&b2[col + 1]);
            float n0 = (acc2[mt][nt][0] - mu0) * rs0 * g0 + be0;
            float n1 = (acc2[mt][nt][1] - mu0) * rs0 * g1 + be1;
            float n2 = (acc2[mt][nt][2] - mu1) * rs1 * g0 + be0;
            float n3 = (acc2[mt][nt][3] - mu1) * rs1 * g1 + be1;
            const size_t p0 = (size_t)((mrow0 + rl0) * 16 + blockIdx.x) * 128 + col;
            const size_t p1 = (size_t)((mrow0 + rl1) * 16 + blockIdx.x) * 128 + col;
            *(__half2*)(yn + p0) =
                __halves2half2(__float2half_rn(n0), __float2half_rn(n1));
            *(__half2*)(yn + p1) =
                __halves2half2(__float2half_rn(n2), __float2half_rn(n3));
        }
    }
}

// ---------------------------------------------------------------------------
// FUSED MLP (R9 proven shape; fp16 residual)
// ---------------------------------------------------------------------------
static constexpr int MLP_SMEM = 12 * TILE_B;

__global__ void __launch_bounds__(512, 1)
k_mlp(const __half* __restrict__ yn,
      const __half* __restrict__ bw1, const __half* __restrict__ bw2,
      const float* __restrict__ b1v, const float* __restrict__ b2v,
      const __half* __restrict__ y, float* __restrict__ out) {
    extern __shared__ __align__(1024) char smem[];
    const uint32_t sb = smem_u32(smem);
    const int tid = threadIdx.x, wid = tid >> 5, lane = tid & 31;
    const int wm = wid & 3, wn = wid >> 2;
    const int mrow0 = blockIdx.x * 128;

    const int a_row = wm * 32 + (lane & 15);
    const int a_kc  = lane >> 4;
    const int b_row = wn * 32 + (lane & 7) + ((lane >> 4) & 1) * 8;
    const int b_kc  = (lane >> 3) & 1;

    load_tile512(sb + 0 * TILE_B, (const char*)yn + (size_t)mrow0 * 256, 256, tid);
    load_tile512(sb + 1 * TILE_B, (const char*)yn + (size_t)mrow0 * 256 + 128, 256, tid);
    load_tile512(sb + 4 * TILE_B, (const char*)bw1, 256, tid);
    load_tile512(sb + 5 * TILE_B, (const char*)bw1 + 128, 256, tid);
    load_tile512(sb + 6 * TILE_B, (const char*)bw2, 1024, tid);
    load_tile512(sb + 7 * TILE_B, (const char*)bw2 + 128, 1024, tid);
    CP_COMMIT();

    float acc2[2][4][4];
    ACC_INIT32(acc2);

    #pragma unroll
    for (int c = 0; c < 4; ++c) {
        if (c) __syncthreads();
        if (c + 1 < 4) {
            uint32_t wb = sb + (uint32_t)(4 + 4 * ((c + 1) & 1)) * TILE_B;
            load_tile512(wb + 0 * TILE_B, (const char*)bw1 + (size_t)(c + 1) * 128 * 256, 256, tid);
            load_tile512(wb + 1 * TILE_B, (const char*)bw1 + (size_t)(c + 1) * 128 * 256 + 128, 256, tid);
            load_tile512(wb + 2 * TILE_B, (const char*)bw2 + (size_t)(c + 1) * 256, 1024, tid);
            load_tile512(wb + 3 * TILE_B, (const char*)bw2 + (size_t)(c + 1) * 256 + 128, 1024, tid);
        }
        CP_COMMIT();
        if (c + 1 < 4) cp_wait<1>(); else cp_wait<0>();
        __syncthreads();

        const uint32_t wb = sb + (uint32_t)(4 + 4 * (c & 1)) * TILE_B;

        float acc1[2][4][4];
        ACC_INIT32(acc1);
        #pragma unroll
        for (int it = 0; it < 2; ++it)
            k64_compute32(sb + (uint32_t)it * TILE_B, wb + (uint32_t)it * TILE_B,
                          a_row, a_kc, b_row, b_kc, acc1);

        #pragma unroll
        for (int mt = 0; mt < 2; ++mt) {
            const int rl0 = wm * 32 + mt * 16 + (lane >> 2);
            #pragma unroll
            for (int nt = 0; nt < 4; ++nt) {
                const int col = wn * 32 + nt * 8 + (lane & 3) * 2;
                float bb0 = __ldg(&b1v[c * 128 + col]);
                float bb1 = __ldg(&b1v[c * 128 + col + 1]);
                float v0 = gelu_exact(acc1[mt][nt][0] + bb0);
                float v1 = gelu_exact(acc1[mt][nt][1] + bb1);
                float v2 = gelu_exact(acc1[mt][nt][2] + bb0);
                float v3 = gelu_exact(acc1[mt][nt][3] + bb1);
                uint32_t t = sb + (uint32_t)(2 + (col >> 6)) * TILE_B;
                sts_h2(t + swz((uint32_t)(rl0 * 128 + (col & 63) * 2)), v0, v1);
                sts_h2(t + swz((uint32_t)((rl0 + 8) * 128 + (col & 63) * 2)), v2, v3);
            }
        }
        __syncthreads();

        #pragma unroll
        for (int it = 0; it < 2; ++it)
            k64_compute32(sb + (uint32_t)(2 + it) * TILE_B,
                          wb + (uint32_t)(2 + it) * TILE_B,
                          a_row, a_kc, b_row, b_kc, acc2);
    }
    __syncthreads();

    float* stg = (float*)smem;
    #pragma unroll
    for (int mt = 0; mt < 2; ++mt) {
        const int rl = wm * 32 + mt * 16 + (lane >> 2);
        #pragma unroll
        for (int nt = 0; nt < 4; ++nt) {
            const int col = wn * 32 + nt * 8 + (lane & 3) * 2;
            float bb0 = __ldg(&b2v[col]), bb1 = __ldg(&b2v[col + 1]);
            const size_t o0 = (size_t)(mrow0 + rl) * 128 + col;
            const size_t o1 = (size_t)(mrow0 + rl + 8) * 128 + col;
            float2 a0 = __half22float2(*(const __half2*)(y + o0));
            float2 a1 = __half22float2(*(const __half2*)(y + o1));
            stg[rl * 132 + col]           = acc2[mt][nt][0] + bb0 + a0.x;
            stg[rl * 132 + col + 1]       = acc2[mt][nt][1] + bb1 + a0.y;
            stg[(rl + 8) * 132 + col]     = acc2[mt][nt][2] + bb0 + a1.x;
            stg[(rl + 8) * 132 + col + 1] = acc2[mt][nt][3] + bb1 + a1.y;
        }
    }
    __syncthreads();

    const int widx0 = blockIdx.x * 8;
    const int b   = widx0 >> 10;
    const int h4  = (widx0 >> 5) & 31;
    const int w40 = widx0 & 31;
    for (int seg = wid; seg < 512; seg += 16) {
        int ch = seg >> 2, hh = seg & 3;
        int row = ((lane >> 2) << 4) + (hh << 2) + (lane & 3);
        float val = stg[row * 132 + ch];
        out[(((size_t)(b * 128 + ch)) * 128 + h4 * 4 + hh) * 128
            + w40 * 4 + lane] = val;
    }
}

// ---------------------------------------------------------------------------
// Launch
// ---------------------------------------------------------------------------
extern "C" void kernel_launch(void* const* d_in, const int* in_sizes, int n_in,
                              void* d_out, int out_size) {
    const float* x      = (const float*)d_in[0];
    const float* gamma1 = (const float*)d_in[1];
    const float* beta1  = (const float*)d_in[2];
    const float* sed_w  = (const float*)d_in[3];
    const float* w_proj = (const float*)d_in[4];
    const float* b_proj = (const float*)d_in[5];
    const float* gamma2 = (const float*)d_in[6];
    const float* beta2  = (const float*)d_in[7];
    const float* w1     = (const float*)d_in[8];
    const float* b1     = (const float*)d_in[9];
    const float* w2     = (const float*)d_in[10];
    const float* b2     = (const float*)d_in[11];
    float* out = (float*)d_out;

    __half *xt, *y, *xn, *yn, *bt, *bp, *bw1, *bw2;
    cudaGetSymbolAddress((void**)&xt, g_xt);
    cudaGetSymbolAddress((void**)&y,  g_y);
    cudaGetSymbolAddress((void**)&xn, g_xn);
    cudaGetSymbolAddress((void**)&yn, g_yn);
    cudaGetSymbolAddress((void**)&bt, g_bt);
    cudaGetSymbolAddress((void**)&bp, g_bp);
    cudaGetSymbolAddress((void**)&bw1, g_b1);
    cudaGetSymbolAddress((void**)&bw2, g_b2);

    cudaFuncSetAttribute(k_sedproj, cudaFuncAttributeMaxDynamicSharedMemorySize, SED_SMEM);
    cudaFuncSetAttribute(k_mlp,     cudaFuncAttributeMaxDynamicSharedMemorySize, MLP_SMEM);

    // 1) LN1 + transpose + all weight preps (single launch)
    k_ln1_prep<<<5120, 256>>>(x, gamma1, beta1, xt, xn,
                              sed_w, w_proj, w1, w2, bt, bp, bw1, bw2);

    // 2) SED + gelu + proj + residual + LN2 (fused)
    k_sedproj<<<dim3(16, 64), 256, SED_SMEM>>>(
        xn, bt, bp, b_proj, xt, gamma2, beta2, y, yn);

    // 3) MLP (fused)
    k_mlp<<<1024, 512, MLP_SMEM>>>(yn, bw1, bw2, b1, b2, y, out);
}

// round 17
// speedup vs baseline: 1.0209x; 1.0151x over previous
#include <cuda_runtime.h>
#include <cuda_fp16.h>
#include <cstdint>
#include <cstddef>

// ---------------------------------------------------------------------------
// Cayley-Dickson sign table:  e_i * e_j = sign(i,j) * e_{i XOR j}
// ---------------------------------------------------------------------------
constexpr int cdsign(int i, int j, int n) {
    return (n == 1) ? 1
         : (i < n/2 && j < n/2) ? cdsign(i, j, n/2)
         : (i < n/2)            ? cdsign(j - n/2, i, n/2)
         : (j < n/2)            ? cdsign(i - n/2, j, n/2) * (j == 0 ? 1 : -1)
         : -cdsign(j - n/2, i - n/2, n/2) * ((j - n/2) == 0 ? 1 : -1);
}
struct SgnTab { signed char v[16][16]; };
constexpr SgnTab make_sgn() {
    SgnTab t{};
    for (int i = 0; i < 16; ++i)
        for (int j = 0; j < 16; ++j)
            t.v[i][j] = (signed char)cdsign(i, j, 16);
    return t;
}
__constant__ SgnTab c_SGN = make_sgn();

// ---------------------------------------------------------------------------
static constexpr int C = 128, NPIX = 8 * 128 * 128;   // 131072

// residual buffers fp16 (calibrated error budget)
__device__ __align__(256) __half g_xt[NPIX * C];
__device__ __align__(256) __half g_y [NPIX * C];

// fp16 operand buffers
__device__ __align__(256) __half g_xn[NPIX * C];
__device__ __align__(256) __half g_yn[NPIX * C];
// weight (B^T, n-major rows of K) buffers
__device__ __align__(256) __half g_bt[2048 * 2048];
__device__ __align__(256) __half g_bp[128 * 128];
__device__ __align__(256) __half g_b1[512 * 128];
__device__ __align__(256) __half g_b2[128 * 512];

// ---------------------------------------------------------------------------
// PTX helpers
// ---------------------------------------------------------------------------
__device__ __forceinline__ uint32_t smem_u32(const void* p) {
    uint32_t a;
    asm("{ .reg .u64 t; cvta.to.shared.u64 t, %1; cvt.u32.u64 %0, t; }"
        : "=r"(a) : "l"(p));
    return a;
}
__device__ __forceinline__ void cp16(uint32_t dst, const void* src) {
    asm volatile("cp.async.cg.shared.global [%0], [%1], 16;" :: "r"(dst), "l"(src));
}
#define CP_COMMIT() asm volatile("cp.async.commit_group;" ::: "memory")
template<int N>
__device__ __forceinline__ void cp_wait() {
    asm volatile("cp.async.wait_group %0;" :: "n"(N) : "memory");
}
__device__ __forceinline__ void ldsm_x4(uint32_t addr, uint32_t* r) {
    asm volatile("ldmatrix.sync.aligned.m8n8.x4.shared.b16 {%0,%1,%2,%3}, [%4];"
        : "=r"(r[0]), "=r"(r[1]), "=r"(r[2]), "=r"(r[3]) : "r"(addr));
}
__device__ __forceinline__ void mma16816(float* c, const uint32_t* a, const uint32_t* b) {
    asm volatile("mma.sync.aligned.m16n8k16.row.col.f32.f16.f16.f32 "
        "{%0,%1,%2,%3}, {%4,%5,%6,%7}, {%8,%9}, {%0,%1,%2,%3};"
        : "+f"(c[0]), "+f"(c[1]), "+f"(c[2]), "+f"(c[3])
        : "r"(a[0]), "r"(a[1]), "r"(a[2]), "r"(a[3]), "r"(b[0]), "r"(b[1]));
}
__device__ __forceinline__ uint32_t swz(uint32_t off) {
    return off ^ ((off >> 3) & 0x70);
}
__device__ __forceinline__ void sts_h2(uint32_t addr, float lo, float hi) {
    __half2 v = __halves2half2(__float2half_rn(lo), __float2half_rn(hi));
    uint32_t u = *reinterpret_cast<uint32_t*>(&v);
    asm volatile("st.shared.b32 [%0], %1;" :: "r"(addr), "r"(u) : "memory");
}
__device__ __forceinline__ float gelu_exact(float v) {
    return 0.5f * v * (1.0f + erff(v * 0.7071067811865476f));
}

static constexpr int TILE_B = 16384;

// Load one K64 tile into smem, swizzled. 256 threads.
__device__ __forceinline__ void load_tile(uint32_t dst, const char* src,
                                          size_t pitch, int tid) {
    #pragma unroll
    for (int i = 0; i < 4; ++i) {
        int l = tid + (i << 8);
        int r = l >> 3, ch = l & 7;
        uint32_t off = (uint32_t)(r * 128 + ch * 16);
        cp16(dst + swz(off), src + (size_t)r * pitch + ch * 16);
    }
}
// Same, 512 threads.
__device__ __forceinline__ void load_tile512(uint32_t dst, const char* src,
                                             size_t pitch, int tid) {
    #pragma unroll
    for (int i = 0; i < 2; ++i) {
        int l = tid + (i << 9);
        int r = l >> 3, ch = l & 7;
        uint32_t off = (uint32_t)(r * 128 + ch * 16);
        cp16(dst + swz(off), src + (size_t)r * pitch + ch * 16);
    }
}

// One K64 compute step, 64-wide warp tile (acc[2][8][4]).
__device__ __forceinline__ void k64_compute(uint32_t bA, uint32_t bB,
        int a_row, int a_kc, int b_row, int b_kc, float acc[2][8][4]) {
    #pragma unroll
    for (int ks = 0; ks < 4; ++ks) {
        uint32_t ar[2][4], bb[4][4];
        #pragma unroll
        for (int mt = 0; mt < 2; ++mt) {
            uint32_t off = swz((uint32_t)((a_row + mt * 16) * 128
                                          + (a_kc + 2 * ks) * 16));
            ldsm_x4(bA + off, ar[mt]);
        }
        #pragma unroll
        for (int nt = 0; nt < 4; ++nt) {
            uint32_t off = swz((uint32_t)((b_row + nt * 16) * 128
                                          + (b_kc + 2 * ks) * 16));
            ldsm_x4(bB + off, bb[nt]);
        }
        #pragma unroll
        for (int mt = 0; mt < 2; ++mt)
            #pragma unroll
            for (int nt = 0; nt < 8; ++nt)
                mma16816(acc[mt][nt], ar[mt], &bb[nt >> 1][(nt & 1) * 2]);
    }
}
// One K64 compute step, 32-wide warp tile (acc[2][4][4]).
__device__ __forceinline__ void k64_compute32(uint32_t bA, uint32_t bB,
        int a_row, int a_kc, int b_row, int b_kc, float acc[2][4][4]) {
    #pragma unroll
    for (int ks = 0; ks < 4; ++ks) {
        uint32_t ar[2][4], bb[2][4];
        #pragma unroll
        for (int mt = 0; mt < 2; ++mt) {
            uint32_t off = swz((uint32_t)((a_row + mt * 16) * 128
                                          + (a_kc + 2 * ks) * 16));
            ldsm_x4(bA + off, ar[mt]);
        }
        #pragma unroll
        for (int nt = 0; nt < 2; ++nt) {
            uint32_t off = swz((uint32_t)((b_row + nt * 16) * 128
                                          + (b_kc + 2 * ks) * 16));
            ldsm_x4(bB + off, bb[nt]);
        }
        #pragma unroll
        for (int mt = 0; mt < 2; ++mt)
            #pragma unroll
            for (int nt = 0; nt < 4; ++nt)
                mma16816(acc[mt][nt], ar[mt], &bb[nt >> 1][(nt & 1) * 2]);
    }
}

#define LANE_IDX(wid, lane)                                        \
    const int wm = (wid) & 3, wn = (wid) >> 2;                     \
    const int a_row = wm * 32 + ((lane) & 15);                     \
    const int a_kc  = ((lane) >> 4);                               \
    const int b_row = wn * 64 + ((lane) & 7) + (((lane) >> 4) & 1) * 8; \
    const int b_kc  = (((lane) >> 3) & 1);

template<int KIT>
__device__ __forceinline__ void gemm_smem(uint32_t aBase, uint32_t bBase,
        int wid, int lane, float acc[2][8][4]) {
    LANE_IDX(wid, lane);
    #pragma unroll
    for (int it = 0; it < KIT; ++it)
        k64_compute(aBase + (uint32_t)it * TILE_B, bBase + (uint32_t)it * TILE_B,
                    a_row, a_kc, b_row, b_kc, acc);
}

#define ACC_INIT(acc)                                  \
    _Pragma("unroll")                                  \
    for (int mt = 0; mt < 2; ++mt)                     \
        _Pragma("unroll")                              \
        for (int nt = 0; nt < 8; ++nt)                 \
            _Pragma("unroll")                          \
            for (int q = 0; q < 4; ++q) acc[mt][nt][q] = 0.f;

#define ACC_INIT32(acc)                                \
    _Pragma("unroll")                                  \
    for (int mt = 0; mt < 2; ++mt)                     \
        _Pragma("unroll")                              \
        for (int nt = 0; nt < 4; ++nt)                 \
            _Pragma("unroll")                          \
            for (int q = 0; q < 4; ++q) acc[mt][nt][q] = 0.f;

// ---------------------------------------------------------------------------
// COMBINED LN1 + weight prep (one launch) — R14 proven
// ---------------------------------------------------------------------------
__global__ void k_ln1_prep(const float* __restrict__ x,
                           const float* __restrict__ g1,
                           const float* __restrict__ b1,
                           __half* __restrict__ xt,
                           __half* __restrict__ xn,
                           const float* __restrict__ sed_w,
                           const float* __restrict__ w_proj,
                           const float* __restrict__ w1,
                           const float* __restrict__ w2,
                           __half* __restrict__ bt, __half* __restrict__ bp,
                           __half* __restrict__ bw1, __half* __restrict__ bw2) {
    __shared__ __align__(16) char shraw[128 * 130 * 2];   // 33280 B, aliased
    const int blk = blockIdx.x;
    const int tid = threadIdx.x;

    if (blk < 4096) {
        // ---------------- LN1 ----------------
        float (*sh)[33]  = (float(*)[33])shraw;
        float (*red)[8][32] = (float(*)[8][32])(shraw + 16896);
        float* smean = (float*)(shraw + 18944);
        float* srstd = (float*)(shraw + 19072);

        const int b  = blk >> 9;
        const int s0 = (blk & 511) * 32;
        const int tp = tid & 31;
        const int ty = tid >> 5;

        const float* xb = x + (size_t)b * 128 * 16384 + s0;
        float sum = 0.f, sq = 0.f;
        #pragma unroll
        for (int c0 = 0; c0 < 128; c0 += 8) {
            int c = c0 + ty;
            float v = xb[(size_t)c * 16384 + tp];
            sh[c][tp] = v;
            sum += v; sq += v * v;
        }
        red[0][ty][tp] = sum; red[1][ty][tp] = sq;
        __syncthreads();
        if (ty == 0) {
            float s = 0.f, q = 0.f;
            #pragma unroll
            for (int y = 0; y < 8; ++y) { s += red[0][y][tp]; q += red[1][y][tp]; }
            float m = s * (1.0f / 128.0f);
            smean[tp] = m;
            srstd[tp] = rsqrtf(q * (1.0f / 128.0f) - m * m + 1e-5f);
        }
        __syncthreads();

        // half2 writeout: 2048 channel-pairs (p = pixel, c = 2*pair)
        #pragma unroll
        for (int li = 0; li < 8; ++li) {
            int l = tid + (li << 8);
            int p = l >> 6, c = (l & 63) * 2;
            int s = s0 + p;
            int hh = s >> 7, ww = s & 127;
            int row = ((((b * 32 + (hh >> 2)) * 32 + (ww >> 2)) << 4)
                      + ((hh & 3) << 2) + (ww & 3));
            float v0 = sh[c][p], v1 = sh[c + 1][p];
            float m = smean[p], rs = srstd[p];
            size_t idx = (size_t)row * 128 + c;
            *(__half2*)(xt + idx) =
                __halves2half2(__float2half_rn(v0), __float2half_rn(v1));
            float n0 = (v0 - m) * rs * g1[c] + b1[c];
            float n1 = (v1 - m) * rs * g1[c + 1] + b1[c + 1];
            *(__half2*)(xn + idx) =
                __halves2half2(__float2half_rn(n0), __float2half_rn(n1));
        }
    } else if (blk < 4352) {
        // ------- SED prep: coalesced transpose, half2 writes -------
        __half (*tile)[130] = (__half(*)[130])shraw;
        const int bi = blk - 4096;
        const int i = bi >> 4, nblk = bi & 15;
        const int j = i ^ nblk;
        const float s = (float)c_SGN.v[i][j];
        const float* src = sed_w + (size_t)j * 16384;
        for (int idx = tid; idx < 16384; idx += 256) {
            int c = idx >> 7, d = idx & 127;
            tile[c][d] = __float2half_rn(s * __ldg(&src[c * 128 + d]));
        }
        __syncthreads();
        // write bt rows (contiguous c), 8192 half2 pairs
        #pragma unroll
        for (int li = 0; li < 32; ++li) {
            int idx = tid + (li << 8);
            int d = idx >> 6, c = (idx & 63) * 2;
            __half2 v = __halves2half2(tile[c][d], tile[c + 1][d]);
            *(__half2*)(bt + (size_t)(nblk * 128 + d) * 2048 + i * 128 + c) = v;
        }
    } else if (blk < 4480) {
        int n = blk - 4352;
        for (int k = tid; k < 128; k += 256)
            bp[(size_t)n * 128 + k] = __float2half_rn(__ldg(&w_proj[(size_t)k * 128 + n]));
    } else if (blk < 4992) {
        int n = blk - 4480;
        for (int k = tid; k < 128; k += 256)
            bw1[(size_t)n * 128 + k] = __float2half_rn(__ldg(&w1[(size_t)k * 512 + n]));
    } else {
        int n = blk - 4992;
        for (int k = tid; k < 512; k += 256)
            bw2[(size_t)n * 512 + k] = __float2half_rn(__ldg(&w2[(size_t)k * 128 + n]));
    }
}

// ---------------------------------------------------------------------------
// FUSED SED + proj + LN2 — inline mainloop with bp prefetch into the dead
// stage slot (tiles 4-5, free after it=29) at it=30; epilogue finds bp
// resident instead of paying a serial gmem round trip.
// ---------------------------------------------------------------------------
static constexpr int SED_SMEM = 3 * 2 * TILE_B;

__global__ void __launch_bounds__(256, 2)
k_sedproj(const __half* __restrict__ A, const __half* __restrict__ B,
          const __half* __restrict__ bp,
          const float* __restrict__ bias, const __half* __restrict__ xt,
          const float* __restrict__ g2, const float* __restrict__ b2,
          __half* __restrict__ y, __half* __restrict__ yn) {
    extern __shared__ __align__(1024) char smem[];
    const uint32_t sb = smem_u32(smem);
    const int tid = threadIdx.x, wid = tid >> 5, lane = tid & 31;
    const int wm = wid & 3, wn = wid >> 2;
    const int mrow0 = blockIdx.y * 128;
    const int n0    = blockIdx.x * 128;

    const int a_row = wm * 32 + (lane & 15);
    const int a_kc  = lane >> 4;
    const int b_row = wn * 64 + (lane & 7) + ((lane >> 4) & 1) * 8;
    const int b_kc  = (lane >> 3) & 1;

    const char* sA = (const char*)A + (size_t)mrow0 * 4096;
    const char* sB = (const char*)B + (size_t)n0 * 4096;

    float acc[2][8][4];
    ACC_INIT(acc);

    // ---- SED mainloop (K=2048, 32 iters, 3-stage) with bp prefetch ----
    auto load_stage = [&](int stage, int kt) {
        load_tile(sb + (uint32_t)(stage * 2 + 0) * TILE_B, sA + (size_t)kt * 128, 4096, tid);
        load_tile(sb + (uint32_t)(stage * 2 + 1) * TILE_B, sB + (size_t)kt * 128, 4096, tid);
    };
    load_stage(0, 0); CP_COMMIT();
    load_stage(1, 1); CP_COMMIT();

    for (int it = 0; it < 32; ++it) {
        cp_wait<1>();
        __syncthreads();
        if (it + 2 < 32) {
            load_stage((it + 2) % 3, it + 2);
        } else if (it == 30) {
            // slot 2 (tiles 4-5) is dead after it=29: prefetch w_proj there
            load_tile(sb + 4 * TILE_B, (const char*)bp, 256, tid);
            load_tile(sb + 5 * TILE_B, (const char*)bp + 128, 256, tid);
        }
        CP_COMMIT();
        const int buf = it % 3;
        k64_compute(sb + (uint32_t)(buf * 2 + 0) * TILE_B,
                    sb + (uint32_t)(buf * 2 + 1) * TILE_B,
                    a_row, a_kc, b_row, b_kc, acc);
    }
    __syncthreads();   // all warps done with final stage before tile 0-1 reuse

    // ---- gelu -> fp16 tiles 0-1 (proj A operand) ----
    #pragma unroll
    for (int mt = 0; mt < 2; ++mt) {
        const int rl0 = wm * 32 + mt * 16 + (lane >> 2);
        #pragma unroll
        for (int nt = 0; nt < 8; ++nt) {
            const int col = wn * 64 + nt * 8 + (lane & 3) * 2;
            float v0 = gelu_exact(acc[mt][nt][0]);
            float v1 = gelu_exact(acc[mt][nt][1]);
            float v2 = gelu_exact(acc[mt][nt][2]);
            float v3 = gelu_exact(acc[mt][nt][3]);
            uint32_t t = sb + (uint32_t)(col >> 6) * TILE_B;
            sts_h2(t + swz((uint32_t)(rl0 * 128 + (col & 63) * 2)), v0, v1);
            sts_h2(t + swz((uint32_t)((rl0 + 8) * 128 + (col & 63) * 2)), v2, v3);
        }
    }
    cp_wait<0>();      // drain bp prefetch (already overlapped with it=30..31)
    __syncthreads();

    // ---- proj GEMM: tiles 0-1 @ tiles 4-5 ----
    float acc2[2][8][4];
    ACC_INIT(acc2);
    gemm_smem<2>(sb, sb + 4 * TILE_B, wid, lane, acc2);

    // ---- pass 1: bias + residual, write y, accumulate LN2 stats ----
    float s_loc[2][2] = {{0.f,0.f},{0.f,0.f}};
    float q_loc[2][2] = {{0.f,0.f},{0.f,0.f}};
    #pragma unroll
    for (int mt = 0; mt < 2; ++mt) {
        const int rl = wm * 32 + mt * 16 + (lane >> 2);
        #pragma unroll
        for (int nt = 0; nt < 8; ++nt) {
            const int col = wn * 64 + nt * 8 + (lane & 3) * 2;
            float bb0 = __ldg(&bias[col]), bb1 = __ldg(&bias[col + 1]);
            const size_t p0 = (size_t)((mrow0 + rl) * 16 + blockIdx.x) * 128 + col;
            const size_t p1 = (size_t)((mrow0 + rl + 8) * 16 + blockIdx.x) * 128 + col;
            float2 a0 = __half22float2(*(const __half2*)(xt + p0));
            float2 a1 = __half22float2(*(const __half2*)(xt + p1));
            float v0 = acc2[mt][nt][0] + bb0 + a0.x;
            float v1 = acc2[mt][nt][1] + bb1 + a0.y;
            float v2 = acc2[mt][nt][2] + bb0 + a1.x;
            float v3 = acc2[mt][nt][3] + bb1 + a1.y;
            *(__half2*)(y + p0) =
                __halves2half2(__float2half_rn(v0), __float2half_rn(v1));
            *(__half2*)(y + p1) =
                __halves2half2(__float2half_rn(v2), __float2half_rn(v3));
            acc2[mt][nt][0] = v0; acc2[mt][nt][1] = v1;
            acc2[mt][nt][2] = v2; acc2[mt][nt][3] = v3;
            s_loc[mt][0] += v0 + v1; q_loc[mt][0] += v0 * v0 + v1 * v1;
            s_loc[mt][1] += v2 + v3; q_loc[mt][1] += v2 * v2 + v3 * v3;
        }
    }
    #pragma unroll
    for (int mt = 0; mt < 2; ++mt)
        #pragma unroll
        for (int h = 0; h < 2; ++h) {
            float s = s_loc[mt][h], q = q_loc[mt][h];
            s += __shfl_xor_sync(0xffffffffu, s, 1);
            s += __shfl_xor_sync(0xffffffffu, s, 2);
            q += __shfl_xor_sync(0xffffffffu, q, 1);
            q += __shfl_xor_sync(0xffffffffu, q, 2);
            s_loc[mt][h] = s; q_loc[mt][h] = q;
        }
    float* rsum = (float*)(smem + 2 * TILE_B);   // tiles 2-3 free (last stage slot 1 consumed)
    float* rsq  = rsum + 256;
    __syncthreads();
    if ((lane & 3) == 0) {
        #pragma unroll
        for (int mt = 0; mt < 2; ++mt)
            #pragma unroll
            for (int h = 0; h < 2; ++h) {
                int rl = wm * 32 + mt * 16 + h * 8 + (lane >> 2);
                rsum[rl * 2 + wn] = s_loc[mt][h];
                rsq [rl * 2 + wn] = q_loc[mt][h];
            }
    }
    __syncthreads();

    // ---- pass 2: LN2 normalize -> fp16 yn ----
    #pragma unroll
    for (int mt = 0; mt < 2; ++mt) {
        const int rl0 = wm * 32 + mt * 16 + (lane >> 2);
        const int rl1 = rl0 + 8;
        float S0 = rsum[rl0 * 2] + rsum[rl0 * 2 + 1];
        float Q0 = rsq [rl0 * 2] + rsq [rl0 * 2 + 1];
        float S1 = rsum[rl1 * 2] + rsum[rl1 * 2 + 1];
        float Q1 = rsq [rl1 * 2] + rsq [rl1 * 2 + 1];
        float mu0 = S0 * (1.0f / 128.0f);
        float rs0 = rsqrtf(Q0 * (1.0f / 128.0f) - mu0 * mu0 + 1e-5f);
        float mu1 = S1 * (1.0f / 128.0f);
        float rs1 = rsqrtf(Q1 * (1.0f / 128.0f) - mu1 * mu1 + 1e-5f);
        #pragma unroll
        for (int nt = 0; nt < 8; ++nt) {
            const int col = wn * 64 + nt * 8 + (lane & 3) * 2;
            float g0 = __ldg(&g2[col]), g1 = __ldg(&g2[col + 1]);
            float be0 = __ldg(&b2[col]), be1 = __ldg(&b2[col + 1]);
            float n0 = (acc2[mt][nt][0] - mu0) * rs0 * g0 + be0;
            float n1 = (acc2[mt][nt][1] - mu0) * rs0 * g1 + be1;
            float n2 = (acc2[mt][nt][2] - mu1) * rs1 * g0 + be0;
            float n3 = (acc2[mt][nt][3] - mu1) * rs1 * g1 + be1;
            const size_t p0 = (size_t)((mrow0 + rl0) * 16 + blockIdx.x) * 128 + col;
            const size_t p1 = (size_t)((mrow0 + rl1) * 16 + blockIdx.x) * 128 + col;
            *(__half2*)(yn + p0) =
                __halves2half2(__float2half_rn(n0), __float2half_rn(n1));
            *(__half2*)(yn + p1) =
                __halves2half2(__float2half_rn(n2), __float2half_rn(n3));
        }
    }
}

// ---------------------------------------------------------------------------
// FUSED MLP (R9 proven shape; fp16 residual)
// ---------------------------------------------------------------------------
static constexpr int MLP_SMEM = 12 * TILE_B;

__global__ void __launch_bounds__(512, 1)
k_mlp(const __half* __restrict__ yn,
      const __half* __restrict__ bw1, const __half* __restrict__ bw2,
      const float* __restrict__ b1v, const float* __restrict__ b2v,
      const __half* __restrict__ y, float* __restrict__ out) {
    extern __shared__ __align__(1024) char smem[];
    const uint32_t sb = smem_u32(smem);
    const int tid = threadIdx.x, wid = tid >> 5, lane = tid & 31;
    const int wm = wid & 3, wn = wid >> 2;
    const int mrow0 = blockIdx.x * 128;

    const int a_row = wm * 32 + (lane & 15);
    const int a_kc  = lane >> 4;
    const int b_row = wn * 32 + (lane & 7) + ((lane >> 4) & 1) * 8;
    const int b_kc  = (lane >> 3) & 1;

    load_tile512(sb + 0 * TILE_B, (const char*)yn + (size_t)mrow0 * 256, 256, tid);
    load_tile512(sb + 1 * TILE_B, (const char*)yn + (size_t)mrow0 * 256 + 128, 256, tid);
    load_tile512(sb + 4 * TILE_B, (const char*)bw1, 256, tid);
    load_tile512(sb + 5 * TILE_B, (const char*)bw1 + 128, 256, tid);
    load_tile512(sb + 6 * TILE_B, (const char*)bw2, 1024, tid);
    load_tile512(sb + 7 * TILE_B, (const char*)bw2 + 128, 1024, tid);
    CP_COMMIT();

    float acc2[2][4][4];
    ACC_INIT32(acc2);

    #pragma unroll
    for (int c = 0; c < 4; ++c) {
        if (c) __syncthreads();
        if (c + 1 < 4) {
            uint32_t wb = sb + (uint32_t)(4 + 4 * ((c + 1) & 1)) * TILE_B;
            load_tile512(wb + 0 * TILE_B, (const char*)bw1 + (size_t)(c + 1) * 128 * 256, 256, tid);
            load_tile512(wb + 1 * TILE_B, (const char*)bw1 + (size_t)(c + 1) * 128 * 256 + 128, 256, tid);
            load_tile512(wb + 2 * TILE_B, (const char*)bw2 + (size_t)(c + 1) * 256, 1024, tid);
            load_tile512(wb + 3 * TILE_B, (const char*)bw2 + (size_t)(c + 1) * 256 + 128, 1024, tid);
        }
        CP_COMMIT();
        if (c + 1 < 4) cp_wait<1>(); else cp_wait<0>();
        __syncthreads();

        const uint32_t wb = sb + (uint32_t)(4 + 4 * (c & 1)) * TILE_B;

        float acc1[2][4][4];
        ACC_INIT32(acc1);
        #pragma unroll
        for (int it = 0; it < 2; ++it)
            k64_compute32(sb + (uint32_t)it * TILE_B, wb + (uint32_t)it * TILE_B,
                          a_row, a_kc, b_row, b_kc, acc1);

        #pragma unroll
        for (int mt = 0; mt < 2; ++mt) {
            const int rl0 = wm * 32 + mt * 16 + (lane >> 2);
            #pragma unroll
            for (int nt = 0; nt < 4; ++nt) {
                const int col = wn * 32 + nt * 8 + (lane & 3) * 2;
                float bb0 = __ldg(&b1v[c * 128 + col]);
                float bb1 = __ldg(&b1v[c * 128 + col + 1]);
                float v0 = gelu_exact(acc1[mt][nt][0] + bb0);
                float v1 = gelu_exact(acc1[mt][nt][1] + bb1);
                float v2 = gelu_exact(acc1[mt][nt][2] + bb0);
                float v3 = gelu_exact(acc1[mt][nt][3] + bb1);
                uint32_t t = sb + (uint32_t)(2 + (col >> 6)) * TILE_B;
                sts_h2(t + swz((uint32_t)(rl0 * 128 + (col & 63) * 2)), v0, v1);
                sts_h2(t + swz((uint32_t)((rl0 + 8) * 128 + (col & 63) * 2)), v2, v3);
            }
        }
        __syncthreads();

        #pragma unroll
        for (int it = 0; it < 2; ++it)
            k64_compute32(sb + (uint32_t)(2 + it) * TILE_B,
                          wb + (uint32_t)(2 + it) * TILE_B,
                          a_row, a_kc, b_row, b_kc, acc2);
    }
    __syncthreads();

    float* stg = (float*)smem;
    #pragma unroll
    for (int mt = 0; mt < 2; ++mt) {
        const int rl = wm * 32 + mt * 16 + (lane >> 2);
        #pragma unroll
        for (int nt = 0; nt < 4; ++nt) {
            const int col = wn * 32 + nt * 8 + (lane & 3) * 2;
            float bb0 = __ldg(&b2v[col]), bb1 = __ldg(&b2v[col + 1]);
            const size_t o0 = (size_t)(mrow0 + rl) * 128 + col;
            const size_t o1 = (size_t)(mrow0 + rl + 8) * 128 + col;
            float2 a0 = __half22float2(*(const __half2*)(y + o0));
            float2 a1 = __half22float2(*(const __half2*)(y + o1));
            stg[rl * 132 + col]           = acc2[mt][nt][0] + bb0 + a0.x;
            stg[rl * 132 + col + 1]       = acc2[mt][nt][1] + bb1 + a0.y;
            stg[(rl + 8) * 132 + col]     = acc2[mt][nt][2] + bb0 + a1.x;
            stg[(rl + 8) * 132 + col + 1] = acc2[mt][nt][3] + bb1 + a1.y;
        }
    }
    __syncthreads();

    const int widx0 = blockIdx.x * 8;
    const int b   = widx0 >> 10;
    const int h4  = (widx0 >> 5) & 31;
    const int w40 = widx0 & 31;
    for (int seg = wid; seg < 512; seg += 16) {
        int ch = seg >> 2, hh = seg & 3;
        int row = ((lane >> 2) << 4) + (hh << 2) + (lane & 3);
        float val = stg[row * 132 + ch];
        out[(((size_t)(b * 128 + ch)) * 128 + h4 * 4 + hh) * 128
            + w40 * 4 + lane] = val;
    }
}

// ---------------------------------------------------------------------------
// Launch
// ---------------------------------------------------------------------------
extern "C" void kernel_launch(void* const* d_in, const int* in_sizes, int n_in,
                              void* d_out, int out_size) {
    const float* x      = (const float*)d_in[0];
    const float* gamma1 = (const float*)d_in[1];
    const float* beta1  = (const float*)d_in[2];
    const float* sed_w  = (const float*)d_in[3];
    const float* w_proj = (const float*)d_in[4];
    const float* b_proj = (const float*)d_in[5];
    const float* gamma2 = (const float*)d_in[6];
    const float* beta2  = (const float*)d_in[7];
    const float* w1     = (const float*)d_in[8];
    const float* b1     = (const float*)d_in[9];
    const float* w2     = (const float*)d_in[10];
    const float* b2     = (const float*)d_in[11];
    float* out = (float*)d_out;

    __half *xt, *y, *xn, *yn, *bt, *bp, *bw1, *bw2;
    cudaGetSymbolAddress((void**)&xt, g_xt);
    cudaGetSymbolAddress((void**)&y,  g_y);
    cudaGetSymbolAddress((void**)&xn, g_xn);
    cudaGetSymbolAddress((void**)&yn, g_yn);
    cudaGetSymbolAddress((void**)&bt, g_bt);
    cudaGetSymbolAddress((void**)&bp, g_bp);
    cudaGetSymbolAddress((void**)&bw1, g_b1);
    cudaGetSymbolAddress((void**)&bw2, g_b2);

    cudaFuncSetAttribute(k_sedproj, cudaFuncAttributeMaxDynamicSharedMemorySize, SED_SMEM);
    cudaFuncSetAttribute(k_mlp,     cudaFuncAttributeMaxDynamicSharedMemorySize, MLP_SMEM);

    // 1) LN1 + transpose + all weight preps (single launch)
    k_ln1_prep<<<5120, 256>>>(x, gamma1, beta1, xt, xn,
                              sed_w, w_proj, w1, w2, bt, bp, bw1, bw2);

    // 2) SED + gelu + proj + residual + LN2 (fused, bp prefetched in-loop)
    k_sedproj<<<dim3(16, 64), 256, SED_SMEM>>>(
        xn, bt, bp, b_proj, xt, gamma2, beta2, y, yn);

    // 3) MLP (fused)
    k_mlp<<<1024, 512, MLP_SMEM>>>(yn, bw1, bw2, b1, b2, y, out);
}